// round 16
// baseline (speedup 1.0000x reference)
#include <cuda_runtime.h>
#include <cuda_fp16.h>
#include <cstdint>

#define D_MODEL 1024
#define D_FF    8192
#define N_ELEM  64
#define D1      128
#define BATCH   2048

__device__ __align__(16) __half g_w1t[(size_t)D_FF * D_MODEL];
__device__ __align__(16) __half g_w2h[(size_t)D_FF * D_MODEL];

// ---------------------------------------------------------------------------
// Prep (merged): blocks [0,4096) transpose+convert w1; [4096,8192) convert w2.
// ---------------------------------------------------------------------------
__global__ __launch_bounds__(256) void prep_kernel(const float* __restrict__ w1,
                                                   const float* __restrict__ w2) {
    __shared__ float tile[32][65];
    const int t = threadIdx.x;
    if (blockIdx.x >= 4096) {
        const size_t i = ((size_t)(blockIdx.x - 4096) * 256 + t) * 8;
        float4 a = *reinterpret_cast<const float4*>(w2 + i);
        float4 b = *reinterpret_cast<const float4*>(w2 + i + 4);
        __half tmp[8];
        tmp[0] = __float2half_rn(a.x); tmp[1] = __float2half_rn(a.y);
        tmp[2] = __float2half_rn(a.z); tmp[3] = __float2half_rn(a.w);
        tmp[4] = __float2half_rn(b.x); tmp[5] = __float2half_rn(b.y);
        tmp[6] = __float2half_rn(b.z); tmp[7] = __float2half_rn(b.w);
        *reinterpret_cast<uint4*>(g_w2h + i) = *reinterpret_cast<const uint4*>(tmp);
        return;
    }
    const int d0  = (blockIdx.x & 31) * 32;
    const int je0 = (blockIdx.x >> 5) * 64;
    const int dr = t >> 5;
    const int c  = (t & 31) * 2;
#pragma unroll
    for (int r = 0; r < 32; r += 8) {
        float2 v = *reinterpret_cast<const float2*>(
            w1 + (size_t)(d0 + r + dr) * D_FF + je0 + c);
        tile[r + dr][c]     = v.x;
        tile[r + dr][c + 1] = v.y;
    }
    __syncthreads();
    const int jl = t >> 2;
    const int ds = (t & 3) * 8;
    __half tmp[8];
#pragma unroll
    for (int i = 0; i < 8; i++) tmp[i] = __float2half_rn(tile[ds + i][jl]);
    *reinterpret_cast<uint4*>(g_w1t + (size_t)(je0 + jl) * D_MODEL + d0 + ds) =
        *reinterpret_cast<const uint4*>(tmp);
}

// ---------------------------------------------------------------------------
// Fused main kernel: one CTA per sample, 256 threads (8 warps).
// Phase A: paired batched LDG.128 + interleaved dual HFMA2 chains; HADD2-tree
//   tail; dual-butterfly warp reduction. (R15, unchanged.)
// Compaction: ballot-scan active-j list; entries (half2-dup r, w2h offset);
//   16 zero pads.
// Phase B: fp16x2 accumulation — per j: LDS.64 + LDG.64 + 2 HFMA2, flushed
//   to fp32 every 16 j. No cvt/pack in the hot loop.
// ---------------------------------------------------------------------------
__global__ __launch_bounds__(256) void fused_kernel(
    const int*   __restrict__ qmask,
    const float* __restrict__ x,
    const float* __restrict__ b2,
    float*       __restrict__ out_res,
    float*       __restrict__ out_mask)
{
    __shared__ __align__(16) __half x_h[D_MODEL];   // 2 KB
    __shared__ float  midr[D1];
    __shared__ int    ms[D1];
    __shared__ uint2  rvo[D1 + 16];                  // (r as half2-dup, offset)
    __shared__ int    wcnt[4];

    const int b = blockIdx.x;
    const int t = threadIdx.x;
    const int w = t >> 5;
    const int l = t & 31;

    // stage x as fp16 + masks
    {
        float4 v = reinterpret_cast<const float4*>(x + (size_t)b * D_MODEL)[t];
        __half2 h0 = __floats2half2_rn(v.x, v.y);
        __half2 h1 = __floats2half2_rn(v.z, v.w);
        uint2 u;
        u.x = *reinterpret_cast<unsigned*>(&h0);
        u.y = *reinterpret_cast<unsigned*>(&h1);
        *reinterpret_cast<uint2*>(x_h + t * 4) = u;
    }
    if (t < D1) {
        int m = qmask[(size_t)b * D1 + t];
        ms[t] = m;
        if (out_mask) out_mask[(size_t)b * D1 + t] = (float)m;
    }
    __syncthreads();

    // ---- Phase A ----
    {
        const uint4* xh4 = reinterpret_cast<const uint4*>(x_h);
        const uint4 xv0 = xh4[l], xv1 = xh4[l + 32], xv2 = xh4[l + 64], xv3 = xh4[l + 96];
        const __half2* xA = reinterpret_cast<const __half2*>(&xv0);
        const __half2* xB = reinterpret_cast<const __half2*>(&xv1);
        const __half2* xC = reinterpret_cast<const __half2*>(&xv2);
        const __half2* xD = reinterpret_cast<const __half2*>(&xv3);

#pragma unroll
        for (int p = 0; p < 8; p++) {
            const int jA = w * 16 + p;
            const int jB = jA + 8;
            const uint4* cpA = reinterpret_cast<const uint4*>(
                g_w1t + (((size_t)jA * N_ELEM + ms[jA]) << 10));
            const uint4* cpB = reinterpret_cast<const uint4*>(
                g_w1t + (((size_t)jB * N_ELEM + ms[jB]) << 10));

            uint4 ua0 = cpA[l], ua1 = cpA[l + 32], ua2 = cpA[l + 64], ua3 = cpA[l + 96];
            uint4 ub0 = cpB[l], ub1 = cpB[l + 32], ub2 = cpB[l + 64], ub3 = cpB[l + 96];

            const __half2* cA0 = reinterpret_cast<const __half2*>(&ua0);
            const __half2* cA1 = reinterpret_cast<const __half2*>(&ua1);
            const __half2* cA2 = reinterpret_cast<const __half2*>(&ua2);
            const __half2* cA3 = reinterpret_cast<const __half2*>(&ua3);
            const __half2* cB0 = reinterpret_cast<const __half2*>(&ub0);
            const __half2* cB1 = reinterpret_cast<const __half2*>(&ub1);
            const __half2* cB2 = reinterpret_cast<const __half2*>(&ub2);
            const __half2* cB3 = reinterpret_cast<const __half2*>(&ub3);

            __half2 a0 = __hmul2(cA0[0], xA[0]);
            __half2 e0 = __hmul2(cB0[0], xA[0]);
            __half2 a1 = __hmul2(cA0[1], xA[1]);
            __half2 e1 = __hmul2(cB0[1], xA[1]);
            __half2 a2 = __hmul2(cA0[2], xA[2]);
            __half2 e2 = __hmul2(cB0[2], xA[2]);
            __half2 a3 = __hmul2(cA0[3], xA[3]);
            __half2 e3 = __hmul2(cB0[3], xA[3]);

            a0 = __hfma2(cA1[0], xB[0], a0);
            e0 = __hfma2(cB1[0], xB[0], e0);
            a1 = __hfma2(cA1[1], xB[1], a1);
            e1 = __hfma2(cB1[1], xB[1], e1);
            a2 = __hfma2(cA1[2], xB[2], a2);
            e2 = __hfma2(cB1[2], xB[2], e2);
            a3 = __hfma2(cA1[3], xB[3], a3);
            e3 = __hfma2(cB1[3], xB[3], e3);

            a0 = __hfma2(cA2[0], xC[0], a0);
            e0 = __hfma2(cB2[0], xC[0], e0);
            a1 = __hfma2(cA2[1], xC[1], a1);
            e1 = __hfma2(cB2[1], xC[1], e1);
            a2 = __hfma2(cA2[2], xC[2], a2);
            e2 = __hfma2(cB2[2], xC[2], e2);
            a3 = __hfma2(cA2[3], xC[3], a3);
            e3 = __hfma2(cB2[3], xC[3], e3);

            a0 = __hfma2(cA3[0], xD[0], a0);
            e0 = __hfma2(cB3[0], xD[0], e0);
            a1 = __hfma2(cA3[1], xD[1], a1);
            e1 = __hfma2(cB3[1], xD[1], e1);
            a2 = __hfma2(cA3[2], xD[2], a2);
            e2 = __hfma2(cB3[2], xD[2], e2);
            a3 = __hfma2(cA3[3], xD[3], a3);
            e3 = __hfma2(cB3[3], xD[3], e3);

            // HADD2 tree tail
            __half2 sa = __hadd2(__hadd2(a0, a1), __hadd2(a2, a3));
            __half2 se = __hadd2(__hadd2(e0, e1), __hadd2(e2, e3));
            float2 fa = __half22float2(sa);
            float2 fe = __half22float2(se);
            float sA = fa.x + fa.y;
            float sB = fe.x + fe.y;

            // dual butterfly: lane0 -> sum(sA), lane1 -> sum(sB)
            float v   = (l & 1) ? sB : sA;
            float oth = (l & 1) ? sA : sB;
            v += __shfl_xor_sync(0xffffffffu, oth, 1);
            v += __shfl_xor_sync(0xffffffffu, v, 2);
            v += __shfl_xor_sync(0xffffffffu, v, 4);
            v += __shfl_xor_sync(0xffffffffu, v, 8);
            v += __shfl_xor_sync(0xffffffffu, v, 16);
            if (l < 2) midr[(l == 0) ? jA : jB] = fmaxf(v, 0.f);
        }
    }
    __syncthreads();

    // ---- Compaction (deterministic, ordered by j) ----
    int nact;
    {
        float cr = 0.f; bool act = false; int widx = 0;
        if (t < D1) {
            cr = midr[t];
            act = cr > 0.f;
            unsigned mb = __ballot_sync(0xffffffffu, act);
            widx = __popc(mb & ((1u << l) - 1u));
            if (l == 0) wcnt[w] = __popc(mb);
        }
        __syncthreads();
        nact = wcnt[0] + wcnt[1] + wcnt[2] + wcnt[3];
        if (act) {
            int base = 0;
#pragma unroll
            for (int q = 0; q < 3; q++) if (w > q) base += wcnt[q];
            __half2 hr = __float2half2_rn(cr);
            rvo[base + widx] = make_uint2(
                *reinterpret_cast<unsigned*>(&hr),
                (unsigned)((ms[t] * D1 + t) << 10));
        }
        // pads [nact, nact+16): r = 0 -> exact no-op
        if (t < 16) rvo[nact + t] = make_uint2(0u, 0u);
        __syncthreads();
    }

    // ---- Phase B: fp16x2 accumulate, fp32 flush every 16 j ----
    {
        const int dbase = t * 4;
        float f0 = 0.f, f1 = 0.f, f2 = 0.f, f3 = 0.f;
        const int kend = (nact + 15) & ~15;

        for (int k = 0; k < kend; k += 16) {
            __half2 A0 = __float2half2_rn(0.f);
            __half2 A1 = A0, B0 = A0, B1 = A0;
#pragma unroll
            for (int u = 0; u < 16; u += 2) {
                uint2 qa = rvo[k + u];
                uint2 qb = rvo[k + u + 1];
                uint2 ha = *reinterpret_cast<const uint2*>(g_w2h + qa.y + dbase);
                uint2 hb = *reinterpret_cast<const uint2*>(g_w2h + qb.y + dbase);
                __half2 ra = *reinterpret_cast<__half2*>(&qa.x);
                __half2 rb = *reinterpret_cast<__half2*>(&qb.x);
                A0 = __hfma2(*reinterpret_cast<__half2*>(&ha.x), ra, A0);
                A1 = __hfma2(*reinterpret_cast<__half2*>(&ha.y), ra, A1);
                B0 = __hfma2(*reinterpret_cast<__half2*>(&hb.x), rb, B0);
                B1 = __hfma2(*reinterpret_cast<__half2*>(&hb.y), rb, B1);
            }
            float2 fa0 = __half22float2(A0);
            float2 fa1 = __half22float2(A1);
            float2 fb0 = __half22float2(B0);
            float2 fb1 = __half22float2(B1);
            f0 += fa0.x + fb0.x;
            f1 += fa0.y + fb0.y;
            f2 += fa1.x + fb1.x;
            f3 += fa1.y + fb1.y;
        }

        float4 bv = reinterpret_cast<const float4*>(b2)[t];
        float4 o;
        o.x = f0 + bv.x;
        o.y = f1 + bv.y;
        o.z = f2 + bv.z;
        o.w = f3 + bv.w;
        reinterpret_cast<float4*>(out_res + (size_t)b * D_MODEL)[t] = o;
    }
}

// ---------------------------------------------------------------------------
extern "C" void kernel_launch(void* const* d_in, const int* in_sizes, int n_in,
                              void* d_out, int out_size) {
    const int*   qmask = nullptr;
    const float* x = nullptr, *w1 = nullptr, *w2 = nullptr, *b2 = nullptr;
    for (int i = 0; i < n_in; i++) {
        const int sz = in_sizes[i];
        if (sz == BATCH * D1)            qmask = (const int*)d_in[i];
        else if (sz == BATCH * D_MODEL)  x     = (const float*)d_in[i];
        else if (sz == D_MODEL)          b2    = (const float*)d_in[i];
        else if (sz == D_MODEL * D_FF) {
            if (!w1) w1 = (const float*)d_in[i];
            else     w2 = (const float*)d_in[i];
        }
    }

    float* out      = (float*)d_out;
    float* out_mask = nullptr;
    float* out_res  = out;
    if (out_size >= BATCH * D1 + BATCH * D_MODEL) {
        out_mask = out;
        out_res  = out + BATCH * D1;
    }

    prep_kernel<<<8192, 256>>>(w1, w2);
    fused_kernel<<<BATCH, 256>>>(qmask, x, b2, out_res, out_mask);
}

// round 17
// speedup vs baseline: 1.0038x; 1.0038x over previous
#include <cuda_runtime.h>
#include <cuda_fp16.h>
#include <cstdint>

#define D_MODEL 1024
#define D_FF    8192
#define N_ELEM  64
#define D1      128
#define BATCH   2048

__device__ __align__(16) __half g_w1t[(size_t)D_FF * D_MODEL];
__device__ __align__(16) __half g_w2h[(size_t)D_FF * D_MODEL];

// ---------------------------------------------------------------------------
// Prep v2: blocks [0,2048) transpose+convert w1 in 32d x 128je tiles (MLP=8);
//          blocks [2048,4096) convert w2, 16 floats/thread (MLP=4).
// ---------------------------------------------------------------------------
__global__ __launch_bounds__(256) void prep_kernel(const float* __restrict__ w1,
                                                   const float* __restrict__ w2) {
    __shared__ float tileA[32][65];
    __shared__ float tileB[32][65];
    const int t = threadIdx.x;

    if (blockIdx.x >= 2048) {
        // ---- w2 convert: 16 floats per thread ----
        const size_t i = ((size_t)(blockIdx.x - 2048) * 256 + t) * 16;
        float4 a = *reinterpret_cast<const float4*>(w2 + i);
        float4 b = *reinterpret_cast<const float4*>(w2 + i + 4);
        float4 c = *reinterpret_cast<const float4*>(w2 + i + 8);
        float4 d = *reinterpret_cast<const float4*>(w2 + i + 12);
        __half tmp[16];
        tmp[0]  = __float2half_rn(a.x); tmp[1]  = __float2half_rn(a.y);
        tmp[2]  = __float2half_rn(a.z); tmp[3]  = __float2half_rn(a.w);
        tmp[4]  = __float2half_rn(b.x); tmp[5]  = __float2half_rn(b.y);
        tmp[6]  = __float2half_rn(b.z); tmp[7]  = __float2half_rn(b.w);
        tmp[8]  = __float2half_rn(c.x); tmp[9]  = __float2half_rn(c.y);
        tmp[10] = __float2half_rn(c.z); tmp[11] = __float2half_rn(c.w);
        tmp[12] = __float2half_rn(d.x); tmp[13] = __float2half_rn(d.y);
        tmp[14] = __float2half_rn(d.z); tmp[15] = __float2half_rn(d.w);
        *reinterpret_cast<uint4*>(g_w2h + i)     = *reinterpret_cast<const uint4*>(tmp);
        *reinterpret_cast<uint4*>(g_w2h + i + 8) = *reinterpret_cast<const uint4*>(tmp + 8);
        return;
    }

    // ---- w1 transpose: tile 32 d-rows x 128 je-cols (two 64-wide halves) ----
    const int d0  = (blockIdx.x & 31) * 32;
    const int je0 = (blockIdx.x >> 5) * 128;
    const int dr  = t >> 5;           // 0..7
    const int c2  = (t & 31) * 2;     // 0..62

#pragma unroll
    for (int r = 0; r < 32; r += 8) {
        const float* rp = w1 + (size_t)(d0 + r + dr) * D_FF + je0;
        float2 vA = *reinterpret_cast<const float2*>(rp + c2);
        float2 vB = *reinterpret_cast<const float2*>(rp + 64 + c2);
        tileA[r + dr][c2]     = vA.x;
        tileA[r + dr][c2 + 1] = vA.y;
        tileB[r + dr][c2]     = vB.x;
        tileB[r + dr][c2 + 1] = vB.y;
    }
    __syncthreads();

    // write out: jl = t>>1 in [0,128), 2 threads per column, 16 d each
    const int jl  = t >> 1;
    const int ds  = (t & 1) * 16;
    const int col = jl & 63;
    const float* src = (jl < 64) ? &tileA[0][0] : &tileB[0][0];
    __half tmp[16];
#pragma unroll
    for (int i = 0; i < 16; i++)
        tmp[i] = __float2half_rn(src[(ds + i) * 65 + col]);
    __half* dst = g_w1t + (size_t)(je0 + jl) * D_MODEL + d0 + ds;
    *reinterpret_cast<uint4*>(dst)     = *reinterpret_cast<const uint4*>(tmp);
    *reinterpret_cast<uint4*>(dst + 8) = *reinterpret_cast<const uint4*>(tmp + 8);
}

// ---------------------------------------------------------------------------
// Fused main kernel (R16, unchanged): one CTA per sample, 256 threads.
// Phase A: paired batched LDG.128 + interleaved dual HFMA2 chains; HADD2-tree
//   tail; dual-butterfly warp reduction.
// Compaction: ballot-scan active-j list; entries (half2-dup r, w2h offset).
// Phase B: fp16x2 accumulation, fp32 flush every 16 j.
// ---------------------------------------------------------------------------
__global__ __launch_bounds__(256) void fused_kernel(
    const int*   __restrict__ qmask,
    const float* __restrict__ x,
    const float* __restrict__ b2,
    float*       __restrict__ out_res,
    float*       __restrict__ out_mask)
{
    __shared__ __align__(16) __half x_h[D_MODEL];   // 2 KB
    __shared__ float  midr[D1];
    __shared__ int    ms[D1];
    __shared__ uint2  rvo[D1 + 16];                  // (r as half2-dup, offset)
    __shared__ int    wcnt[4];

    const int b = blockIdx.x;
    const int t = threadIdx.x;
    const int w = t >> 5;
    const int l = t & 31;

    // stage x as fp16 + masks
    {
        float4 v = reinterpret_cast<const float4*>(x + (size_t)b * D_MODEL)[t];
        __half2 h0 = __floats2half2_rn(v.x, v.y);
        __half2 h1 = __floats2half2_rn(v.z, v.w);
        uint2 u;
        u.x = *reinterpret_cast<unsigned*>(&h0);
        u.y = *reinterpret_cast<unsigned*>(&h1);
        *reinterpret_cast<uint2*>(x_h + t * 4) = u;
    }
    if (t < D1) {
        int m = qmask[(size_t)b * D1 + t];
        ms[t] = m;
        if (out_mask) out_mask[(size_t)b * D1 + t] = (float)m;
    }
    __syncthreads();

    // ---- Phase A ----
    {
        const uint4* xh4 = reinterpret_cast<const uint4*>(x_h);
        const uint4 xv0 = xh4[l], xv1 = xh4[l + 32], xv2 = xh4[l + 64], xv3 = xh4[l + 96];
        const __half2* xA = reinterpret_cast<const __half2*>(&xv0);
        const __half2* xB = reinterpret_cast<const __half2*>(&xv1);
        const __half2* xC = reinterpret_cast<const __half2*>(&xv2);
        const __half2* xD = reinterpret_cast<const __half2*>(&xv3);

#pragma unroll
        for (int p = 0; p < 8; p++) {
            const int jA = w * 16 + p;
            const int jB = jA + 8;
            const uint4* cpA = reinterpret_cast<const uint4*>(
                g_w1t + (((size_t)jA * N_ELEM + ms[jA]) << 10));
            const uint4* cpB = reinterpret_cast<const uint4*>(
                g_w1t + (((size_t)jB * N_ELEM + ms[jB]) << 10));

            uint4 ua0 = cpA[l], ua1 = cpA[l + 32], ua2 = cpA[l + 64], ua3 = cpA[l + 96];
            uint4 ub0 = cpB[l], ub1 = cpB[l + 32], ub2 = cpB[l + 64], ub3 = cpB[l + 96];

            const __half2* cA0 = reinterpret_cast<const __half2*>(&ua0);
            const __half2* cA1 = reinterpret_cast<const __half2*>(&ua1);
            const __half2* cA2 = reinterpret_cast<const __half2*>(&ua2);
            const __half2* cA3 = reinterpret_cast<const __half2*>(&ua3);
            const __half2* cB0 = reinterpret_cast<const __half2*>(&ub0);
            const __half2* cB1 = reinterpret_cast<const __half2*>(&ub1);
            const __half2* cB2 = reinterpret_cast<const __half2*>(&ub2);
            const __half2* cB3 = reinterpret_cast<const __half2*>(&ub3);

            __half2 a0 = __hmul2(cA0[0], xA[0]);
            __half2 e0 = __hmul2(cB0[0], xA[0]);
            __half2 a1 = __hmul2(cA0[1], xA[1]);
            __half2 e1 = __hmul2(cB0[1], xA[1]);
            __half2 a2 = __hmul2(cA0[2], xA[2]);
            __half2 e2 = __hmul2(cB0[2], xA[2]);
            __half2 a3 = __hmul2(cA0[3], xA[3]);
            __half2 e3 = __hmul2(cB0[3], xA[3]);

            a0 = __hfma2(cA1[0], xB[0], a0);
            e0 = __hfma2(cB1[0], xB[0], e0);
            a1 = __hfma2(cA1[1], xB[1], a1);
            e1 = __hfma2(cB1[1], xB[1], e1);
            a2 = __hfma2(cA1[2], xB[2], a2);
            e2 = __hfma2(cB1[2], xB[2], e2);
            a3 = __hfma2(cA1[3], xB[3], a3);
            e3 = __hfma2(cB1[3], xB[3], e3);

            a0 = __hfma2(cA2[0], xC[0], a0);
            e0 = __hfma2(cB2[0], xC[0], e0);
            a1 = __hfma2(cA2[1], xC[1], a1);
            e1 = __hfma2(cB2[1], xC[1], e1);
            a2 = __hfma2(cA2[2], xC[2], a2);
            e2 = __hfma2(cB2[2], xC[2], e2);
            a3 = __hfma2(cA2[3], xC[3], a3);
            e3 = __hfma2(cB2[3], xC[3], e3);

            a0 = __hfma2(cA3[0], xD[0], a0);
            e0 = __hfma2(cB3[0], xD[0], e0);
            a1 = __hfma2(cA3[1], xD[1], a1);
            e1 = __hfma2(cB3[1], xD[1], e1);
            a2 = __hfma2(cA3[2], xD[2], a2);
            e2 = __hfma2(cB3[2], xD[2], e2);
            a3 = __hfma2(cA3[3], xD[3], a3);
            e3 = __hfma2(cB3[3], xD[3], e3);

            // HADD2 tree tail
            __half2 sa = __hadd2(__hadd2(a0, a1), __hadd2(a2, a3));
            __half2 se = __hadd2(__hadd2(e0, e1), __hadd2(e2, e3));
            float2 fa = __half22float2(sa);
            float2 fe = __half22float2(se);
            float sA = fa.x + fa.y;
            float sB = fe.x + fe.y;

            // dual butterfly: lane0 -> sum(sA), lane1 -> sum(sB)
            float v   = (l & 1) ? sB : sA;
            float oth = (l & 1) ? sA : sB;
            v += __shfl_xor_sync(0xffffffffu, oth, 1);
            v += __shfl_xor_sync(0xffffffffu, v, 2);
            v += __shfl_xor_sync(0xffffffffu, v, 4);
            v += __shfl_xor_sync(0xffffffffu, v, 8);
            v += __shfl_xor_sync(0xffffffffu, v, 16);
            if (l < 2) midr[(l == 0) ? jA : jB] = fmaxf(v, 0.f);
        }
    }
    __syncthreads();

    // ---- Compaction (deterministic, ordered by j) ----
    int nact;
    {
        float cr = 0.f; bool act = false; int widx = 0;
        if (t < D1) {
            cr = midr[t];
            act = cr > 0.f;
            unsigned mb = __ballot_sync(0xffffffffu, act);
            widx = __popc(mb & ((1u << l) - 1u));
            if (l == 0) wcnt[w] = __popc(mb);
        }
        __syncthreads();
        nact = wcnt[0] + wcnt[1] + wcnt[2] + wcnt[3];
        if (act) {
            int base = 0;
#pragma unroll
            for (int q = 0; q < 3; q++) if (w > q) base += wcnt[q];
            __half2 hr = __float2half2_rn(cr);
            rvo[base + widx] = make_uint2(
                *reinterpret_cast<unsigned*>(&hr),
                (unsigned)((ms[t] * D1 + t) << 10));
        }
        // pads [nact, nact+16): r = 0 -> exact no-op
        if (t < 16) rvo[nact + t] = make_uint2(0u, 0u);
        __syncthreads();
    }

    // ---- Phase B: fp16x2 accumulate, fp32 flush every 16 j ----
    {
        const int dbase = t * 4;
        float f0 = 0.f, f1 = 0.f, f2 = 0.f, f3 = 0.f;
        const int kend = (nact + 15) & ~15;

        for (int k = 0; k < kend; k += 16) {
            __half2 A0 = __float2half2_rn(0.f);
            __half2 A1 = A0, B0 = A0, B1 = A0;
#pragma unroll
            for (int u = 0; u < 16; u += 2) {
                uint2 qa = rvo[k + u];
                uint2 qb = rvo[k + u + 1];
                uint2 ha = *reinterpret_cast<const uint2*>(g_w2h + qa.y + dbase);
                uint2 hb = *reinterpret_cast<const uint2*>(g_w2h + qb.y + dbase);
                __half2 ra = *reinterpret_cast<__half2*>(&qa.x);
                __half2 rb = *reinterpret_cast<__half2*>(&qb.x);
                A0 = __hfma2(*reinterpret_cast<__half2*>(&ha.x), ra, A0);
                A1 = __hfma2(*reinterpret_cast<__half2*>(&ha.y), ra, A1);
                B0 = __hfma2(*reinterpret_cast<__half2*>(&hb.x), rb, B0);
                B1 = __hfma2(*reinterpret_cast<__half2*>(&hb.y), rb, B1);
            }
            float2 fa0 = __half22float2(A0);
            float2 fa1 = __half22float2(A1);
            float2 fb0 = __half22float2(B0);
            float2 fb1 = __half22float2(B1);
            f0 += fa0.x + fb0.x;
            f1 += fa0.y + fb0.y;
            f2 += fa1.x + fb1.x;
            f3 += fa1.y + fb1.y;
        }

        float4 bv = reinterpret_cast<const float4*>(b2)[t];
        float4 o;
        o.x = f0 + bv.x;
        o.y = f1 + bv.y;
        o.z = f2 + bv.z;
        o.w = f3 + bv.w;
        reinterpret_cast<float4*>(out_res + (size_t)b * D_MODEL)[t] = o;
    }
}

// ---------------------------------------------------------------------------
extern "C" void kernel_launch(void* const* d_in, const int* in_sizes, int n_in,
                              void* d_out, int out_size) {
    const int*   qmask = nullptr;
    const float* x = nullptr, *w1 = nullptr, *w2 = nullptr, *b2 = nullptr;
    for (int i = 0; i < n_in; i++) {
        const int sz = in_sizes[i];
        if (sz == BATCH * D1)            qmask = (const int*)d_in[i];
        else if (sz == BATCH * D_MODEL)  x     = (const float*)d_in[i];
        else if (sz == D_MODEL)          b2    = (const float*)d_in[i];
        else if (sz == D_MODEL * D_FF) {
            if (!w1) w1 = (const float*)d_in[i];
            else     w2 = (const float*)d_in[i];
        }
    }

    float* out      = (float*)d_out;
    float* out_mask = nullptr;
    float* out_res  = out;
    if (out_size >= BATCH * D1 + BATCH * D_MODEL) {
        out_mask = out;
        out_res  = out + BATCH * D1;
    }

    prep_kernel<<<4096, 256>>>(w1, w2);
    fused_kernel<<<BATCH, 256>>>(qmask, x, b2, out_res, out_mask);
}